// round 2
// baseline (speedup 1.0000x reference)
#include <cuda_runtime.h>
#include <math.h>

#define NN 50000
#define EG 800000
#define EE 850000   // EG + NN self loops

// ---------------- scratch (device globals; no allocation) ----------------
__device__ __align__(16) float g_h1[NN * 128];          // layer1 linear out / relu out (reused)
__device__ __align__(16) float g_agg1[NN * 128];        // layer1 aggregated
__device__ __align__(16) float g_as1[NN * 4];
__device__ __align__(16) float g_ad1[NN * 4];
__device__ __align__(16) float g_max1[NN * 4];
__device__ __align__(16) float g_sum1[NN * 4];
__device__ __align__(16) float g_alpha1[(size_t)EE * 4]; // alpha then exp(alpha-max)
__device__ __align__(16) float g_h2[NN * 32];
__device__ __align__(16) float g_agg2[NN * 32];
__device__ __align__(16) float g_as2[NN];
__device__ __align__(16) float g_ad2[NN];
__device__ __align__(16) float g_max2[NN];
__device__ __align__(16) float g_sum2[NN];
__device__ __align__(16) float g_alpha2[EE];

// ---------------- helpers ----------------
__device__ __forceinline__ float lrelu(float x) { return x > 0.f ? x : 0.2f * x; }

__device__ __forceinline__ void atomicMaxF(float* addr, float v) {
    if (v >= 0.f) atomicMax((int*)addr, __float_as_int(v));
    else          atomicMin((unsigned int*)addr, __float_as_uint(v));
}

__device__ __forceinline__ void redAdd4(float* addr, float a, float b, float c, float d) {
    asm volatile("red.global.add.v4.f32 [%0], {%1,%2,%3,%4};"
                 :: "l"(addr), "f"(a), "f"(b), "f"(c), "f"(d) : "memory");
}

// ---------------- GEMM1: g_h1 = x[NN,128] @ W1[128,128] ----------------
__global__ void gemm1_kernel(const float* __restrict__ x, const float* __restrict__ W) {
    __shared__ float sW[64 * 128];  // 32KB (k-tile x 128 cols)
    __shared__ float sX[32 * 64];   // 8KB  (32 rows x k-tile)
    const int tid = threadIdx.x;    // 128 threads, one output column each
    const int row0 = blockIdx.x * 32;

    float acc[32];
#pragma unroll
    for (int r = 0; r < 32; r++) acc[r] = 0.f;

    for (int kt = 0; kt < 128; kt += 64) {
        __syncthreads();
#pragma unroll
        for (int i = 0; i < 16; i++) {
            int idx = tid + i * 128;
            ((float4*)sW)[idx] = ((const float4*)(W + (size_t)kt * 128))[idx];
        }
#pragma unroll
        for (int i = 0; i < 4; i++) {
            int idx = tid + i * 128;            // 0..511
            int r = idx >> 4, kc = idx & 15;    // 16 float4 per row-chunk
            int row = row0 + r;
            float4 v = make_float4(0.f, 0.f, 0.f, 0.f);
            if (row < NN) v = ((const float4*)(x + (size_t)row * 128 + kt))[kc];
            ((float4*)sX)[r * 16 + kc] = v;
        }
        __syncthreads();
        for (int k = 0; k < 64; k++) {
            float w = sW[k * 128 + tid];
#pragma unroll
            for (int r = 0; r < 32; r++) acc[r] += sX[r * 64 + k] * w;
        }
    }
#pragma unroll
    for (int r = 0; r < 32; r++) {
        int row = row0 + r;
        if (row < NN) g_h1[(size_t)row * 128 + tid] = acc[r];
    }
}

// ---------------- node prep layer1: attention halves + seg init ----------------
__global__ void nodeprep1_kernel(const float* __restrict__ a_src, const float* __restrict__ a_dst) {
    int i = blockIdx.x * blockDim.x + threadIdx.x;
    if (i >= NN * 4) return;
    int n = i >> 2, h = i & 3;
    const float4* hp = (const float4*)(g_h1 + (size_t)n * 128 + h * 32);
    const float4* asv = (const float4*)(a_src + h * 32);
    const float4* adv = (const float4*)(a_dst + h * 32);
    float s = 0.f, d = 0.f;
#pragma unroll
    for (int c = 0; c < 8; c++) {
        float4 hv = hp[c], av = __ldg(&asv[c]), bv = __ldg(&adv[c]);
        s += hv.x * av.x + hv.y * av.y + hv.z * av.z + hv.w * av.w;
        d += hv.x * bv.x + hv.y * bv.y + hv.z * bv.z + hv.w * bv.w;
    }
    g_as1[i] = s;
    g_ad1[i] = d;
    g_max1[i] = -INFINITY;
    g_sum1[i] = 0.f;
}

// ---------------- zero helper (float4 grid-stride) ----------------
__global__ void zero4_kernel(float4* p, int count4) {
    int i = blockIdx.x * blockDim.x + threadIdx.x;
    int stride = gridDim.x * blockDim.x;
    float4 z = make_float4(0.f, 0.f, 0.f, 0.f);
    for (; i < count4; i += stride) p[i] = z;
}

// ---------------- edge pass A layer1: alpha + segment max ----------------
__global__ void edgeA1_kernel(const int* __restrict__ ei) {
    int e = blockIdx.x * blockDim.x + threadIdx.x;
    if (e >= EE) return;
    int s, d;
    if (e < EG) { s = ei[e]; d = ei[EG + e]; }
    else        { s = d = e - EG; }
    float4 as = *(const float4*)(g_as1 + (size_t)s * 4);
    float4 ad = *(const float4*)(g_ad1 + (size_t)d * 4);
    float4 a;
    a.x = lrelu(as.x + ad.x);
    a.y = lrelu(as.y + ad.y);
    a.z = lrelu(as.z + ad.z);
    a.w = lrelu(as.w + ad.w);
    *(float4*)(g_alpha1 + (size_t)e * 4) = a;
    float* m = g_max1 + (size_t)d * 4;
    atomicMaxF(m + 0, a.x);
    atomicMaxF(m + 1, a.y);
    atomicMaxF(m + 2, a.z);
    atomicMaxF(m + 3, a.w);
}

// ---------------- edge pass B layer1: exp + segment sum ----------------
__global__ void edgeB1_kernel(const int* __restrict__ ei) {
    int e = blockIdx.x * blockDim.x + threadIdx.x;
    if (e >= EE) return;
    int d;
    if (e < EG) d = ei[EG + e];
    else        d = e - EG;
    float4 a = *(const float4*)(g_alpha1 + (size_t)e * 4);
    float4 m = *(const float4*)(g_max1 + (size_t)d * 4);
    float4 ev;
    ev.x = __expf(a.x - m.x);
    ev.y = __expf(a.y - m.y);
    ev.z = __expf(a.z - m.z);
    ev.w = __expf(a.w - m.w);
    *(float4*)(g_alpha1 + (size_t)e * 4) = ev;
    redAdd4(g_sum1 + (size_t)d * 4, ev.x, ev.y, ev.z, ev.w);
}

// ---------------- edge pass C layer1: weighted scatter (warp per edge) ----------------
__global__ void edgeC1_kernel(const int* __restrict__ ei) {
    int warp = (blockIdx.x * blockDim.x + threadIdx.x) >> 5;
    int lane = threadIdx.x & 31;
    if (warp >= EE) return;
    int e = warp;
    int s, d;
    if (e < EG) { s = ei[e]; d = ei[EG + e]; }
    else        { s = d = e - EG; }
    int head = lane >> 3;                       // 8 lanes (32 ch) per head
    float ev = g_alpha1[(size_t)e * 4 + head];
    float denom = g_sum1[(size_t)d * 4 + head];
    float w = ev / fmaxf(denom, 1e-16f);
    float4 hv = *(const float4*)(g_h1 + (size_t)s * 128 + lane * 4);
    redAdd4(g_agg1 + (size_t)d * 128 + lane * 4, hv.x * w, hv.y * w, hv.z * w, hv.w * w);
}

// ---------------- finalize layer1: relu(agg + b1) -> g_h1 ----------------
__global__ void fin1_kernel(const float* __restrict__ b1) {
    int i = blockIdx.x * blockDim.x + threadIdx.x;
    if (i >= NN * 128) return;
    g_h1[i] = fmaxf(g_agg1[i] + __ldg(&b1[i & 127]), 0.f);
}

// ---------------- GEMM2: g_h2 = g_h1[NN,128] @ W2[128,32] ----------------
__global__ void gemm2_kernel(const float* __restrict__ W2) {
    __shared__ float sW[128 * 32];  // 16KB
    __shared__ float sX[32 * 128];  // 16KB
    const int tid = threadIdx.x;    // 256
    const int row0 = blockIdx.x * 32;
    for (int i = tid; i < 1024; i += 256)
        ((float4*)sW)[i] = ((const float4*)W2)[i];
    for (int i = tid; i < 1024; i += 256) {
        int r = i >> 5, kc = i & 31;
        int row = row0 + r;
        float4 v = make_float4(0.f, 0.f, 0.f, 0.f);
        if (row < NN) v = ((const float4*)(g_h1 + (size_t)row * 128))[kc];
        ((float4*)sX)[i] = v;
    }
    __syncthreads();
    int col = tid & 31, rbase = tid >> 5;  // 8 row-groups of 4
    float acc[4] = {0.f, 0.f, 0.f, 0.f};
    for (int k = 0; k < 128; k++) {
        float w = sW[k * 32 + col];
#pragma unroll
        for (int j = 0; j < 4; j++) acc[j] += sX[(rbase + 8 * j) * 128 + k] * w;
    }
#pragma unroll
    for (int j = 0; j < 4; j++) {
        int row = row0 + rbase + 8 * j;
        if (row < NN) g_h2[(size_t)row * 32 + col] = acc[j];
    }
}

// ---------------- node prep layer2 ----------------
__global__ void nodeprep2_kernel(const float* __restrict__ a_src, const float* __restrict__ a_dst) {
    int n = blockIdx.x * blockDim.x + threadIdx.x;
    if (n >= NN) return;
    const float4* hp = (const float4*)(g_h2 + (size_t)n * 32);
    float s = 0.f, d = 0.f;
#pragma unroll
    for (int c = 0; c < 8; c++) {
        float4 hv = hp[c];
        float4 av = __ldg(&((const float4*)a_src)[c]);
        float4 bv = __ldg(&((const float4*)a_dst)[c]);
        s += hv.x * av.x + hv.y * av.y + hv.z * av.z + hv.w * av.w;
        d += hv.x * bv.x + hv.y * bv.y + hv.z * bv.z + hv.w * bv.w;
    }
    g_as2[n] = s;
    g_ad2[n] = d;
    g_max2[n] = -INFINITY;
    g_sum2[n] = 0.f;
}

// ---------------- edge pass A layer2 ----------------
__global__ void edgeA2_kernel(const int* __restrict__ ei) {
    int e = blockIdx.x * blockDim.x + threadIdx.x;
    if (e >= EE) return;
    int s, d;
    if (e < EG) { s = ei[e]; d = ei[EG + e]; }
    else        { s = d = e - EG; }
    float a = lrelu(g_as2[s] + g_ad2[d]);
    g_alpha2[e] = a;
    atomicMaxF(&g_max2[d], a);
}

// ---------------- edge pass B layer2 ----------------
__global__ void edgeB2_kernel(const int* __restrict__ ei) {
    int e = blockIdx.x * blockDim.x + threadIdx.x;
    if (e >= EE) return;
    int d;
    if (e < EG) d = ei[EG + e];
    else        d = e - EG;
    float ev = __expf(g_alpha2[e] - g_max2[d]);
    g_alpha2[e] = ev;
    atomicAdd(&g_sum2[d], ev);
}

// ---------------- edge pass C layer2: 8 lanes per edge ----------------
__global__ void edgeC2_kernel(const int* __restrict__ ei) {
    int gthread = blockIdx.x * blockDim.x + threadIdx.x;
    int e = gthread >> 3;        // 8 lanes per edge
    int j = gthread & 7;         // float4 chunk within 32 channels
    if (e >= EE) return;
    int s, d;
    if (e < EG) { s = ei[e]; d = ei[EG + e]; }
    else        { s = d = e - EG; }
    float w = g_alpha2[e] / fmaxf(g_sum2[d], 1e-16f);
    float4 hv = *(const float4*)(g_h2 + (size_t)s * 32 + j * 4);
    redAdd4(g_agg2 + (size_t)d * 32 + j * 4, hv.x * w, hv.y * w, hv.z * w, hv.w * w);
}

// ---------------- finalize layer2: sigmoid(agg + b2) -> out ----------------
__global__ void fin2_kernel(float* __restrict__ out, const float* __restrict__ b2) {
    int i = blockIdx.x * blockDim.x + threadIdx.x;
    if (i >= NN * 32) return;
    float v = g_agg2[i] + __ldg(&b2[i & 31]);
    out[i] = 1.f / (1.f + __expf(-v));
}

// ---------------- launcher ----------------
extern "C" void kernel_launch(void* const* d_in, const int* in_sizes, int n_in,
                              void* d_out, int out_size) {
    const float* x      = (const float*)d_in[0];
    const int*   ei     = (const int*)d_in[1];   // JAX coerces int64 -> int32 (no x64)
    const float* W1     = (const float*)d_in[2];
    const float* a_src1 = (const float*)d_in[3];
    const float* a_dst1 = (const float*)d_in[4];
    const float* b1     = (const float*)d_in[5];
    const float* W2     = (const float*)d_in[6];
    const float* a_src2 = (const float*)d_in[7];
    const float* a_dst2 = (const float*)d_in[8];
    const float* b2     = (const float*)d_in[9];
    float* out = (float*)d_out;

    float* agg1_ptr = nullptr;
    float* agg2_ptr = nullptr;
    cudaGetSymbolAddress((void**)&agg1_ptr, g_agg1);
    cudaGetSymbolAddress((void**)&agg2_ptr, g_agg2);

    // -------- layer 1 --------
    gemm1_kernel<<<(NN + 31) / 32, 128>>>(x, W1);
    nodeprep1_kernel<<<(NN * 4 + 255) / 256, 256>>>(a_src1, a_dst1);
    zero4_kernel<<<2048, 256>>>((float4*)agg1_ptr, NN * 128 / 4);
    edgeA1_kernel<<<(EE + 255) / 256, 256>>>(ei);
    edgeB1_kernel<<<(EE + 255) / 256, 256>>>(ei);
    edgeC1_kernel<<<(EE + 7) / 8, 256>>>(ei);       // warp per edge
    fin1_kernel<<<(NN * 128 + 255) / 256, 256>>>(b1);

    // -------- layer 2 --------
    gemm2_kernel<<<(NN + 31) / 32, 256>>>(W2);
    nodeprep2_kernel<<<(NN + 255) / 256, 256>>>(a_src2, a_dst2);
    zero4_kernel<<<1024, 256>>>((float4*)agg2_ptr, NN * 32 / 4);
    edgeA2_kernel<<<(EE + 255) / 256, 256>>>(ei);
    edgeB2_kernel<<<(EE + 255) / 256, 256>>>(ei);
    edgeC2_kernel<<<(EE * 8 + 255) / 256, 256>>>(ei); // 8 lanes per edge
    fin2_kernel<<<(NN * 32 + 255) / 256, 256>>>(out, b2);
}

// round 3
// speedup vs baseline: 1.8644x; 1.8644x over previous
#include <cuda_runtime.h>
#include <math.h>

#define NN 50000
#define EG 800000
#define EE 850000            // EG + NN self loops
#define NB1 196              // ceil(NN/256)

// ---------------- scratch (device globals; no allocation) ----------------
__device__ __align__(16) float g_h1[NN * 128];   // layer1 linear out
__device__ __align__(16) float g_o1[NN * 128];   // layer1 aggregated+relu out
__device__ __align__(16) float g_h2[NN * 32];    // layer2 linear out
__device__ __align__(16) float g_as1[NN * 4];
__device__ __align__(16) float g_ad1[NN * 4];
__device__ __align__(16) float g_as2[NN];
__device__ __align__(16) float g_ad2[NN];
__device__ int g_deg[NN];
__device__ int g_rowstart[NN];
__device__ int g_cursor[NN];
__device__ int g_psum[NB1];
__device__ int g_boff[NB1];
__device__ int g_csrc[EE];

__device__ __forceinline__ float lrelu(float x) { return x > 0.f ? x : 0.2f * x; }

// ================= CSR build =================
__global__ void hist_init_kernel() {
    int n = blockIdx.x * blockDim.x + threadIdx.x;
    if (n < NN) g_deg[n] = 1;              // self loop
}

__global__ void hist_kernel(const int* __restrict__ ei) {
    int e = blockIdx.x * blockDim.x + threadIdx.x;
    if (e < EG) atomicAdd(&g_deg[ei[EG + e]], 1);
}

// block reduce partial sums of g_deg
__global__ void scan1_kernel() {
    __shared__ int sm[256];
    int t = threadIdx.x;
    int idx = blockIdx.x * 256 + t;
    sm[t] = (idx < NN) ? g_deg[idx] : 0;
    __syncthreads();
#pragma unroll
    for (int off = 128; off > 0; off >>= 1) {
        if (t < off) sm[t] += sm[t + off];
        __syncthreads();
    }
    if (t == 0) g_psum[blockIdx.x] = sm[0];
}

__device__ __forceinline__ int blockScanExclusive(int v, int* sm) {
    int t = threadIdx.x;
    sm[t] = v;
    __syncthreads();
#pragma unroll
    for (int off = 1; off < 256; off <<= 1) {
        int x = (t >= off) ? sm[t - off] : 0;
        __syncthreads();
        sm[t] += x;
        __syncthreads();
    }
    return sm[t] - v;
}

__global__ void scan2_kernel() {   // 1 block, 256 threads
    __shared__ int sm[256];
    int t = threadIdx.x;
    int v = (t < NB1) ? g_psum[t] : 0;
    int ex = blockScanExclusive(v, sm);
    if (t < NB1) g_boff[t] = ex;
}

__global__ void scan3_kernel() {
    __shared__ int sm[256];
    int t = threadIdx.x;
    int idx = blockIdx.x * 256 + t;
    int v = (idx < NN) ? g_deg[idx] : 0;
    int ex = blockScanExclusive(v, sm) + g_boff[blockIdx.x];
    if (idx < NN) {
        g_rowstart[idx] = ex;
        g_cursor[idx] = ex;
    }
}

__global__ void scatter_kernel(const int* __restrict__ ei) {
    int e = blockIdx.x * blockDim.x + threadIdx.x;
    if (e >= EE) return;
    int s, d;
    if (e < EG) { s = ei[e]; d = ei[EG + e]; }
    else        { s = d = e - EG; }
    int pos = atomicAdd(&g_cursor[d], 1);
    g_csrc[pos] = s;
}

// ================= GEMM1: g_h1 = x[NN,128] @ W1[128,128] =================
// block 256 threads, tile 64 rows x 128 cols, thread: 8 rows x 4 cols
__global__ void gemm1_kernel(const float* __restrict__ x, const float* __restrict__ W) {
    __shared__ float sX[64 * 32];   // 8KB  (rows x ktile)
    __shared__ float sW[32 * 128];  // 16KB (ktile x cols)
    const int t = threadIdx.x;
    const int row0 = blockIdx.x * 64;
    const int cg = (t & 31) * 4;    // col base
    const int rg = (t >> 5) * 8;    // row base

    float acc[8][4];
#pragma unroll
    for (int j = 0; j < 8; j++)
#pragma unroll
        for (int q = 0; q < 4; q++) acc[j][q] = 0.f;

    for (int kt = 0; kt < 128; kt += 32) {
        __syncthreads();
#pragma unroll
        for (int i = 0; i < 2; i++) {
            int idx = t + i * 256;          // 0..511
            int r = idx >> 3, kc = idx & 7;
            int row = row0 + r;
            float4 v = make_float4(0.f, 0.f, 0.f, 0.f);
            if (row < NN) v = *(const float4*)(x + (size_t)row * 128 + kt + kc * 4);
            *(float4*)(sX + r * 32 + kc * 4) = v;
        }
#pragma unroll
        for (int i = 0; i < 4; i++) {
            int idx = t + i * 256;          // 0..1023
            int k = idx >> 5, c = idx & 31;
            *(float4*)(sW + k * 128 + c * 4) = *(const float4*)(W + (size_t)(kt + k) * 128 + c * 4);
        }
        __syncthreads();
#pragma unroll
        for (int k = 0; k < 32; k++) {
            float4 wv = *(const float4*)(sW + k * 128 + cg);
#pragma unroll
            for (int j = 0; j < 8; j++) {
                float xv = sX[(rg + j) * 32 + k];
                acc[j][0] += xv * wv.x;
                acc[j][1] += xv * wv.y;
                acc[j][2] += xv * wv.z;
                acc[j][3] += xv * wv.w;
            }
        }
    }
#pragma unroll
    for (int j = 0; j < 8; j++) {
        int row = row0 + rg + j;
        if (row < NN)
            *(float4*)(g_h1 + (size_t)row * 128 + cg) =
                make_float4(acc[j][0], acc[j][1], acc[j][2], acc[j][3]);
    }
}

// ================= node prep layer1 =================
__global__ void nodeprep1_kernel(const float* __restrict__ a_src, const float* __restrict__ a_dst) {
    int i = blockIdx.x * blockDim.x + threadIdx.x;
    if (i >= NN * 4) return;
    int n = i >> 2, h = i & 3;
    const float4* hp = (const float4*)(g_h1 + (size_t)n * 128 + h * 32);
    const float4* asv = (const float4*)(a_src + h * 32);
    const float4* adv = (const float4*)(a_dst + h * 32);
    float s = 0.f, d = 0.f;
#pragma unroll
    for (int c = 0; c < 8; c++) {
        float4 hv = hp[c], av = __ldg(&asv[c]), bv = __ldg(&adv[c]);
        s += hv.x * av.x + hv.y * av.y + hv.z * av.z + hv.w * av.w;
        d += hv.x * bv.x + hv.y * bv.y + hv.z * bv.z + hv.w * bv.w;
    }
    g_as1[i] = s;
    g_ad1[i] = d;
}

// ================= fused layer1: warp per node, online softmax =================
__global__ void fused1_kernel(const float* __restrict__ b1) {
    int warp = (blockIdx.x * blockDim.x + threadIdx.x) >> 5;
    int lane = threadIdx.x & 31;
    if (warp >= NN) return;
    int d = warp;
    int head = lane >> 3;
    int start = g_rowstart[d];
    int end = start + g_deg[d];
    float ad = g_ad1[d * 4 + head];

    float m = -INFINITY, ssum = 0.f;
    float4 acc = make_float4(0.f, 0.f, 0.f, 0.f);

    for (int i = start; i < end; i++) {
        int s = g_csrc[i];
        float as = g_as1[s * 4 + head];
        float a = lrelu(as + ad);
        float mn = fmaxf(m, a);
        float corr = __expf(m - mn);     // first iter: exp(-inf)=0
        float p = __expf(a - mn);
        ssum = ssum * corr + p;
        float4 hv = *(const float4*)(g_h1 + (size_t)s * 128 + lane * 4);
        acc.x = acc.x * corr + p * hv.x;
        acc.y = acc.y * corr + p * hv.y;
        acc.z = acc.z * corr + p * hv.z;
        acc.w = acc.w * corr + p * hv.w;
        m = mn;
    }
    float inv = 1.f / fmaxf(ssum, 1e-16f);
    float4 bv = __ldg(&((const float4*)b1)[lane]);
    float4 o;
    o.x = fmaxf(acc.x * inv + bv.x, 0.f);
    o.y = fmaxf(acc.y * inv + bv.y, 0.f);
    o.z = fmaxf(acc.z * inv + bv.z, 0.f);
    o.w = fmaxf(acc.w * inv + bv.w, 0.f);
    *(float4*)(g_o1 + (size_t)d * 128 + lane * 4) = o;
}

// ================= GEMM2: g_h2 = g_o1[NN,128] @ W2[128,32] =================
__global__ void gemm2_kernel(const float* __restrict__ W2) {
    __shared__ float sX[64 * 128];  // 32KB
    __shared__ float sW[128 * 32];  // 16KB
    const int t = threadIdx.x;
    const int row0 = blockIdx.x * 64;
    for (int i = t; i < 1024; i += 256)
        ((float4*)sW)[i] = ((const float4*)W2)[i];
    for (int i = t; i < 2048; i += 256) {
        int r = i >> 5, kc = i & 31;
        int row = row0 + r;
        float4 v = make_float4(0.f, 0.f, 0.f, 0.f);
        if (row < NN) v = *(const float4*)(g_o1 + (size_t)row * 128 + kc * 4);
        ((float4*)sX)[i] = v;
    }
    __syncthreads();
    int c = t & 31, rg = (t >> 5) * 8;
    float acc[8];
#pragma unroll
    for (int j = 0; j < 8; j++) acc[j] = 0.f;
    for (int k = 0; k < 128; k++) {
        float w = sW[k * 32 + c];
#pragma unroll
        for (int j = 0; j < 8; j++) acc[j] += sX[(rg + j) * 128 + k] * w;
    }
#pragma unroll
    for (int j = 0; j < 8; j++) {
        int row = row0 + rg + j;
        if (row < NN) g_h2[(size_t)row * 32 + c] = acc[j];
    }
}

// ================= node prep layer2 =================
__global__ void nodeprep2_kernel(const float* __restrict__ a_src, const float* __restrict__ a_dst) {
    int n = blockIdx.x * blockDim.x + threadIdx.x;
    if (n >= NN) return;
    const float4* hp = (const float4*)(g_h2 + (size_t)n * 32);
    float s = 0.f, d = 0.f;
#pragma unroll
    for (int c = 0; c < 8; c++) {
        float4 hv = hp[c];
        float4 av = __ldg(&((const float4*)a_src)[c]);
        float4 bv = __ldg(&((const float4*)a_dst)[c]);
        s += hv.x * av.x + hv.y * av.y + hv.z * av.z + hv.w * av.w;
        d += hv.x * bv.x + hv.y * bv.y + hv.z * bv.z + hv.w * bv.w;
    }
    g_as2[n] = s;
    g_ad2[n] = d;
}

// ================= fused layer2: warp per node, online softmax, sigmoid out =================
__global__ void fused2_kernel(float* __restrict__ out, const float* __restrict__ b2) {
    int warp = (blockIdx.x * blockDim.x + threadIdx.x) >> 5;
    int lane = threadIdx.x & 31;
    if (warp >= NN) return;
    int d = warp;
    int start = g_rowstart[d];
    int end = start + g_deg[d];
    float ad = g_ad2[d];

    float m = -INFINITY, ssum = 0.f, acc = 0.f;
    for (int i = start; i < end; i++) {
        int s = g_csrc[i];
        float as = g_as2[s];
        float a = lrelu(as + ad);
        float mn = fmaxf(m, a);
        float corr = __expf(m - mn);
        float p = __expf(a - mn);
        ssum = ssum * corr + p;
        float hv = g_h2[(size_t)s * 32 + lane];
        acc = acc * corr + p * hv;
        m = mn;
    }
    float v = acc / fmaxf(ssum, 1e-16f) + __ldg(&b2[lane]);
    out[(size_t)d * 32 + lane] = 1.f / (1.f + __expf(-v));
}

// ================= launcher =================
extern "C" void kernel_launch(void* const* d_in, const int* in_sizes, int n_in,
                              void* d_out, int out_size) {
    const float* x      = (const float*)d_in[0];
    const int*   ei     = (const int*)d_in[1];   // JAX coerces int64 -> int32
    const float* W1     = (const float*)d_in[2];
    const float* a_src1 = (const float*)d_in[3];
    const float* a_dst1 = (const float*)d_in[4];
    const float* b1     = (const float*)d_in[5];
    const float* W2     = (const float*)d_in[6];
    const float* a_src2 = (const float*)d_in[7];
    const float* a_dst2 = (const float*)d_in[8];
    const float* b2     = (const float*)d_in[9];
    float* out = (float*)d_out;

    // CSR build (shared by both layers)
    hist_init_kernel<<<(NN + 255) / 256, 256>>>();
    hist_kernel<<<(EG + 255) / 256, 256>>>(ei);
    scan1_kernel<<<NB1, 256>>>();
    scan2_kernel<<<1, 256>>>();
    scan3_kernel<<<NB1, 256>>>();
    scatter_kernel<<<(EE + 255) / 256, 256>>>(ei);

    // layer 1
    gemm1_kernel<<<(NN + 63) / 64, 256>>>(x, W1);
    nodeprep1_kernel<<<(NN * 4 + 255) / 256, 256>>>(a_src1, a_dst1);
    fused1_kernel<<<(NN * 32 + 255) / 256, 256>>>(b1);

    // layer 2
    gemm2_kernel<<<(NN + 63) / 64, 256>>>(W2);
    nodeprep2_kernel<<<(NN + 255) / 256, 256>>>(a_src2, a_dst2);
    fused2_kernel<<<(NN * 32 + 255) / 256, 256>>>(out, b2);
}

// round 4
// speedup vs baseline: 2.1383x; 1.1469x over previous
#include <cuda_runtime.h>
#include <math.h>

#define NN 50000
#define EG 800000
#define EE 850000            // EG + NN self loops
#define NB1 196              // ceil(NN/256)

// ---------------- scratch (device globals; no allocation) ----------------
__device__ __align__(16) float g_h1[NN * 128];   // layer1 linear out
__device__ __align__(16) float g_o1[NN * 128];   // layer1 aggregated+relu out
__device__ __align__(16) float g_h2[NN * 32];    // layer2 linear out
__device__ __align__(16) float g_as1[NN * 4];
__device__ __align__(16) float g_ad1[NN * 4];
__device__ __align__(16) float g_as2[NN];
__device__ __align__(16) float g_ad2[NN];
__device__ int g_deg[NN];
__device__ int g_rowstart[NN];
__device__ int g_cursor[NN];
__device__ int g_psum[NB1];
__device__ int g_boff[NB1];
__device__ int g_csrc[EE];

__device__ __forceinline__ float lrelu(float x) { return x > 0.f ? x : 0.2f * x; }

// ================= CSR build =================
__global__ void hist_init_kernel() {
    int n = blockIdx.x * blockDim.x + threadIdx.x;
    if (n < NN) g_deg[n] = 1;              // self loop
}

__global__ void hist_kernel(const int* __restrict__ ei) {
    int e = blockIdx.x * blockDim.x + threadIdx.x;
    if (e < EG) atomicAdd(&g_deg[ei[EG + e]], 1);
}

__global__ void scan1_kernel() {
    __shared__ int sm[256];
    int t = threadIdx.x;
    int idx = blockIdx.x * 256 + t;
    sm[t] = (idx < NN) ? g_deg[idx] : 0;
    __syncthreads();
#pragma unroll
    for (int off = 128; off > 0; off >>= 1) {
        if (t < off) sm[t] += sm[t + off];
        __syncthreads();
    }
    if (t == 0) g_psum[blockIdx.x] = sm[0];
}

__device__ __forceinline__ int blockScanExclusive(int v, int* sm) {
    int t = threadIdx.x;
    sm[t] = v;
    __syncthreads();
#pragma unroll
    for (int off = 1; off < 256; off <<= 1) {
        int x = (t >= off) ? sm[t - off] : 0;
        __syncthreads();
        sm[t] += x;
        __syncthreads();
    }
    return sm[t] - v;
}

__global__ void scan2_kernel() {   // 1 block, 256 threads
    __shared__ int sm[256];
    int t = threadIdx.x;
    int v = (t < NB1) ? g_psum[t] : 0;
    int ex = blockScanExclusive(v, sm);
    if (t < NB1) g_boff[t] = ex;
}

__global__ void scan3_kernel() {
    __shared__ int sm[256];
    int t = threadIdx.x;
    int idx = blockIdx.x * 256 + t;
    int v = (idx < NN) ? g_deg[idx] : 0;
    int ex = blockScanExclusive(v, sm) + g_boff[blockIdx.x];
    if (idx < NN) {
        g_rowstart[idx] = ex;
        g_cursor[idx] = ex;
    }
}

__global__ void scatter_kernel(const int* __restrict__ ei) {
    int e = blockIdx.x * blockDim.x + threadIdx.x;
    if (e >= EE) return;
    int s, d;
    if (e < EG) { s = ei[e]; d = ei[EG + e]; }
    else        { s = d = e - EG; }
    int pos = atomicAdd(&g_cursor[d], 1);
    g_csrc[pos] = s;
}

// ================= GEMM1 + fused attention-halves epilogue =================
// tile 128 rows x 128 cols, 256 threads, each thread 8x8.
__global__ void gemm1_kernel(const float* __restrict__ x, const float* __restrict__ W,
                             const float* __restrict__ a_src, const float* __restrict__ a_dst) {
    __shared__ float sX[128 * 32];  // 16KB
    __shared__ float sW[32 * 128];  // 16KB
    const int t = threadIdx.x;
    const int tx = t & 15;          // col group (8 cols)
    const int ty = t >> 4;          // row group (8 rows)
    const int row0 = blockIdx.x * 128;

    float acc[8][8];
#pragma unroll
    for (int j = 0; j < 8; j++)
#pragma unroll
        for (int q = 0; q < 8; q++) acc[j][q] = 0.f;

    for (int kt = 0; kt < 128; kt += 32) {
        __syncthreads();
#pragma unroll
        for (int i = 0; i < 4; i++) {
            int idx = t + i * 256;          // 0..1023
            int r = idx >> 3, kq = idx & 7;
            int row = row0 + r;
            float4 v = make_float4(0.f, 0.f, 0.f, 0.f);
            if (row < NN) v = *(const float4*)(x + (size_t)row * 128 + kt + kq * 4);
            *(float4*)(sX + r * 32 + kq * 4) = v;
        }
#pragma unroll
        for (int i = 0; i < 4; i++) {
            int idx = t + i * 256;
            int k = idx >> 5, cq = idx & 31;
            *(float4*)(sW + k * 128 + cq * 4) = *(const float4*)(W + (size_t)(kt + k) * 128 + cq * 4);
        }
        __syncthreads();
#pragma unroll
        for (int k = 0; k < 32; k++) {
            float4 w0 = *(const float4*)(sW + k * 128 + tx * 8);
            float4 w1 = *(const float4*)(sW + k * 128 + tx * 8 + 4);
#pragma unroll
            for (int j = 0; j < 8; j++) {
                float xv = sX[(ty * 8 + j) * 32 + k];
                acc[j][0] += xv * w0.x; acc[j][1] += xv * w0.y;
                acc[j][2] += xv * w0.z; acc[j][3] += xv * w0.w;
                acc[j][4] += xv * w1.x; acc[j][5] += xv * w1.y;
                acc[j][6] += xv * w1.z; acc[j][7] += xv * w1.w;
            }
        }
    }

    // attention-half vectors for this thread's 8 columns
    float4 av0 = __ldg((const float4*)(a_src + tx * 8));
    float4 av1 = __ldg((const float4*)(a_src + tx * 8 + 4));
    float4 bv0 = __ldg((const float4*)(a_dst + tx * 8));
    float4 bv1 = __ldg((const float4*)(a_dst + tx * 8 + 4));
    int head = tx >> 2;

#pragma unroll
    for (int j = 0; j < 8; j++) {
        int row = row0 + ty * 8 + j;
        float ps = acc[j][0] * av0.x + acc[j][1] * av0.y + acc[j][2] * av0.z + acc[j][3] * av0.w
                 + acc[j][4] * av1.x + acc[j][5] * av1.y + acc[j][6] * av1.z + acc[j][7] * av1.w;
        float pd = acc[j][0] * bv0.x + acc[j][1] * bv0.y + acc[j][2] * bv0.z + acc[j][3] * bv0.w
                 + acc[j][4] * bv1.x + acc[j][5] * bv1.y + acc[j][6] * bv1.z + acc[j][7] * bv1.w;
        ps += __shfl_xor_sync(0xffffffff, ps, 1);
        ps += __shfl_xor_sync(0xffffffff, ps, 2);
        pd += __shfl_xor_sync(0xffffffff, pd, 1);
        pd += __shfl_xor_sync(0xffffffff, pd, 2);
        if (row < NN) {
            *(float4*)(g_h1 + (size_t)row * 128 + tx * 8) =
                make_float4(acc[j][0], acc[j][1], acc[j][2], acc[j][3]);
            *(float4*)(g_h1 + (size_t)row * 128 + tx * 8 + 4) =
                make_float4(acc[j][4], acc[j][5], acc[j][6], acc[j][7]);
            if ((tx & 3) == 0) {
                g_as1[row * 4 + head] = ps;
                g_ad1[row * 4 + head] = pd;
            }
        }
    }
}

// ================= fused layer1: warp per node, softmax (no max shift) =================
__global__ void fused1_kernel(const float* __restrict__ b1) {
    int warp = (blockIdx.x * blockDim.x + threadIdx.x) >> 5;
    int lane = threadIdx.x & 31;
    if (warp >= NN) return;
    int d = warp;
    int head = lane >> 3;
    int start = g_rowstart[d];
    int end = start + g_deg[d];
    float ad = g_ad1[d * 4 + head];

    float ssum = 0.f;
    float4 acc = make_float4(0.f, 0.f, 0.f, 0.f);
    for (int i = start; i < end; i++) {
        int s = g_csrc[i];
        float p = __expf(lrelu(g_as1[s * 4 + head] + ad));
        ssum += p;
        float4 hv = *(const float4*)(g_h1 + (size_t)s * 128 + lane * 4);
        acc.x += p * hv.x;
        acc.y += p * hv.y;
        acc.z += p * hv.z;
        acc.w += p * hv.w;
    }
    float inv = 1.f / fmaxf(ssum, 1e-16f);
    float4 bv = __ldg(&((const float4*)b1)[lane]);
    float4 o;
    o.x = fmaxf(acc.x * inv + bv.x, 0.f);
    o.y = fmaxf(acc.y * inv + bv.y, 0.f);
    o.z = fmaxf(acc.z * inv + bv.z, 0.f);
    o.w = fmaxf(acc.w * inv + bv.w, 0.f);
    *(float4*)(g_o1 + (size_t)d * 128 + lane * 4) = o;
}

// ================= GEMM2 + fused attention-halves epilogue =================
__global__ void gemm2_kernel(const float* __restrict__ W2,
                             const float* __restrict__ a_src, const float* __restrict__ a_dst) {
    __shared__ float sX[64 * 128];  // 32KB
    __shared__ float sW[128 * 32];  // 16KB
    const int t = threadIdx.x;      // 256
    const int row0 = blockIdx.x * 64;
    for (int i = t; i < 1024; i += 256)
        ((float4*)sW)[i] = ((const float4*)W2)[i];
    for (int i = t; i < 2048; i += 256) {
        int r = i >> 5, kc = i & 31;
        int row = row0 + r;
        float4 v = make_float4(0.f, 0.f, 0.f, 0.f);
        if (row < NN) v = *(const float4*)(g_o1 + (size_t)row * 128 + kc * 4);
        ((float4*)sX)[i] = v;
    }
    __syncthreads();
    int c = t & 31, rg = (t >> 5) * 8;
    float acc[8];
#pragma unroll
    for (int j = 0; j < 8; j++) acc[j] = 0.f;
    for (int k = 0; k < 128; k++) {
        float w = sW[k * 32 + c];
#pragma unroll
        for (int j = 0; j < 8; j++) acc[j] += sX[(rg + j) * 128 + k] * w;
    }
    float asc = __ldg(a_src + c);
    float adc = __ldg(a_dst + c);
#pragma unroll
    for (int j = 0; j < 8; j++) {
        int row = row0 + rg + j;
        float sp = acc[j] * asc;
        float dp = acc[j] * adc;
#pragma unroll
        for (int off = 16; off > 0; off >>= 1) {
            sp += __shfl_xor_sync(0xffffffff, sp, off);
            dp += __shfl_xor_sync(0xffffffff, dp, off);
        }
        if (row < NN) {
            g_h2[(size_t)row * 32 + c] = acc[j];
            if (c == 0) { g_as2[row] = sp; g_ad2[row] = dp; }
        }
    }
}

// ================= fused layer2: warp per node, softmax, sigmoid out =================
__global__ void fused2_kernel(float* __restrict__ out, const float* __restrict__ b2) {
    int warp = (blockIdx.x * blockDim.x + threadIdx.x) >> 5;
    int lane = threadIdx.x & 31;
    if (warp >= NN) return;
    int d = warp;
    int start = g_rowstart[d];
    int end = start + g_deg[d];
    float ad = g_ad2[d];

    float ssum = 0.f, acc = 0.f;
    for (int i = start; i < end; i++) {
        int s = g_csrc[i];
        float p = __expf(lrelu(g_as2[s] + ad));
        ssum += p;
        acc += p * g_h2[(size_t)s * 32 + lane];
    }
    float v = acc / fmaxf(ssum, 1e-16f) + __ldg(&b2[lane]);
    out[(size_t)d * 32 + lane] = 1.f / (1.f + __expf(-v));
}

// ================= launcher =================
extern "C" void kernel_launch(void* const* d_in, const int* in_sizes, int n_in,
                              void* d_out, int out_size) {
    const float* x      = (const float*)d_in[0];
    const int*   ei     = (const int*)d_in[1];   // JAX coerces int64 -> int32
    const float* W1     = (const float*)d_in[2];
    const float* a_src1 = (const float*)d_in[3];
    const float* a_dst1 = (const float*)d_in[4];
    const float* b1     = (const float*)d_in[5];
    const float* W2     = (const float*)d_in[6];
    const float* a_src2 = (const float*)d_in[7];
    const float* a_dst2 = (const float*)d_in[8];
    const float* b2     = (const float*)d_in[9];
    float* out = (float*)d_out;

    static cudaStream_t s2 = nullptr;
    static cudaEvent_t evFork = nullptr, evJoin = nullptr;
    if (s2 == nullptr) {
        cudaStreamCreateWithFlags(&s2, cudaStreamNonBlocking);
        cudaEventCreateWithFlags(&evFork, cudaEventDisableTiming);
        cudaEventCreateWithFlags(&evJoin, cudaEventDisableTiming);
    }

    // fork: CSR build on s2, GEMM1 on main stream (independent)
    cudaEventRecord(evFork, 0);
    cudaStreamWaitEvent(s2, evFork, 0);

    hist_init_kernel<<<(NN + 255) / 256, 256, 0, s2>>>();
    hist_kernel<<<(EG + 255) / 256, 256, 0, s2>>>(ei);
    scan1_kernel<<<NB1, 256, 0, s2>>>();
    scan2_kernel<<<1, 256, 0, s2>>>();
    scan3_kernel<<<NB1, 256, 0, s2>>>();
    scatter_kernel<<<(EE + 255) / 256, 256, 0, s2>>>(ei);
    cudaEventRecord(evJoin, s2);

    gemm1_kernel<<<(NN + 127) / 128, 256>>>(x, W1, a_src1, a_dst1);

    // join: fused1 needs CSR + gemm1
    cudaStreamWaitEvent(0, evJoin, 0);
    fused1_kernel<<<(NN * 32 + 255) / 256, 256>>>(b1);

    gemm2_kernel<<<(NN + 63) / 64, 256>>>(W2, a_src2, a_dst2);
    fused2_kernel<<<(NN * 32 + 255) / 256, 256>>>(out, b2);
}

// round 5
// speedup vs baseline: 2.5989x; 1.2154x over previous
#include <cuda_runtime.h>
#include <cuda_fp16.h>
#include <math.h>

#define NN 50000
#define EG 800000
#define EE 850000            // EG + NN self loops
#define NB1 196              // ceil(NN/256)

// ---------------- scratch (device globals; no allocation) ----------------
__device__ __align__(16) __half g_h1h[NN * 128];  // layer1 linear out (fp16, gather-only)
__device__ __align__(16) float g_o1[NN * 128];    // layer1 aggregated+relu out
__device__ __align__(16) __half g_h2h[NN * 32];   // layer2 linear out (fp16, gather-only)
__device__ __align__(16) float g_as1[NN * 4];
__device__ __align__(16) float g_ad1[NN * 4];
__device__ __align__(16) float g_as2[NN];
__device__ __align__(16) float g_ad2[NN];
__device__ int g_deg[NN];        // real in-degree (self-loop folded as +1 by consumers)
__device__ int g_rowstart[NN];   // block-LOCAL exclusive scan
__device__ int g_cursor[NN];     // block-LOCAL cursor
__device__ int g_psum[NB1];
__device__ int g_boff[NB1];      // per-block global offset
__device__ int g_csrc[EE];

__device__ __forceinline__ float lrelu(float x) { return x > 0.f ? x : 0.2f * x; }

// ================= CSR build (5 kernels) =================
__global__ void zero_deg_kernel() {
    int n = blockIdx.x * blockDim.x + threadIdx.x;
    if (n < NN) g_deg[n] = 0;
}

__global__ void hist_kernel(const int* __restrict__ ei) {
    int e = blockIdx.x * blockDim.x + threadIdx.x;
    if (e < EG) atomicAdd(&g_deg[ei[EG + e]], 1);
}

__device__ __forceinline__ int blockScanExclusive(int v, int* sm) {
    int t = threadIdx.x;
    sm[t] = v;
    __syncthreads();
#pragma unroll
    for (int off = 1; off < 256; off <<= 1) {
        int x = (t >= off) ? sm[t - off] : 0;
        __syncthreads();
        sm[t] += x;
        __syncthreads();
    }
    return sm[t] - v;
}

// local exclusive scan of (deg+1) per 256-node block; block total -> psum
__global__ void scanA_kernel() {
    __shared__ int sm[256];
    int t = threadIdx.x;
    int idx = blockIdx.x * 256 + t;
    int v = (idx < NN) ? g_deg[idx] + 1 : 0;
    int ex = blockScanExclusive(v, sm);
    if (idx < NN) {
        g_rowstart[idx] = ex;
        g_cursor[idx] = ex;
    }
    if (t == 255) g_psum[blockIdx.x] = ex + v;
}

__global__ void scanB_kernel() {   // 1 block, 256 threads
    __shared__ int sm[256];
    int t = threadIdx.x;
    int v = (t < NB1) ? g_psum[t] : 0;
    int ex = blockScanExclusive(v, sm);
    if (t < NB1) g_boff[t] = ex;
}

__global__ void scatter_kernel(const int* __restrict__ ei) {
    int e = blockIdx.x * blockDim.x + threadIdx.x;
    if (e >= EE) return;
    int s, d;
    if (e < EG) { s = ei[e]; d = ei[EG + e]; }
    else        { s = d = e - EG; }
    int pos = atomicAdd(&g_cursor[d], 1) + g_boff[d >> 8];
    g_csrc[pos] = s;
}

// ================= GEMM1 + fused attention-halves epilogue =================
// tile 128 rows x 128 cols, 256 threads, each thread 8x8. fp16 h1 output.
__global__ void gemm1_kernel(const float* __restrict__ x, const float* __restrict__ W,
                             const float* __restrict__ a_src, const float* __restrict__ a_dst) {
    __shared__ float sX[128 * 36];  // stride 36 to kill bank conflicts (18KB)
    __shared__ float sW[32 * 128];  // 16KB
    const int t = threadIdx.x;
    const int tx = t & 15;          // col group (8 cols)
    const int ty = t >> 4;          // row group (8 rows)
    const int row0 = blockIdx.x * 128;

    float acc[8][8];
#pragma unroll
    for (int j = 0; j < 8; j++)
#pragma unroll
        for (int q = 0; q < 8; q++) acc[j][q] = 0.f;

    for (int kt = 0; kt < 128; kt += 32) {
        __syncthreads();
#pragma unroll
        for (int i = 0; i < 4; i++) {
            int idx = t + i * 256;          // 0..1023
            int r = idx >> 3, kq = idx & 7;
            int row = row0 + r;
            float4 v = make_float4(0.f, 0.f, 0.f, 0.f);
            if (row < NN) v = *(const float4*)(x + (size_t)row * 128 + kt + kq * 4);
            *(float4*)(sX + r * 36 + kq * 4) = v;
        }
#pragma unroll
        for (int i = 0; i < 4; i++) {
            int idx = t + i * 256;
            int k = idx >> 5, cq = idx & 31;
            *(float4*)(sW + k * 128 + cq * 4) = *(const float4*)(W + (size_t)(kt + k) * 128 + cq * 4);
        }
        __syncthreads();
#pragma unroll
        for (int k = 0; k < 32; k++) {
            float4 w0 = *(const float4*)(sW + k * 128 + tx * 8);
            float4 w1 = *(const float4*)(sW + k * 128 + tx * 8 + 4);
#pragma unroll
            for (int j = 0; j < 8; j++) {
                float xv = sX[(ty * 8 + j) * 36 + k];
                acc[j][0] += xv * w0.x; acc[j][1] += xv * w0.y;
                acc[j][2] += xv * w0.z; acc[j][3] += xv * w0.w;
                acc[j][4] += xv * w1.x; acc[j][5] += xv * w1.y;
                acc[j][6] += xv * w1.z; acc[j][7] += xv * w1.w;
            }
        }
    }

    float4 av0 = __ldg((const float4*)(a_src + tx * 8));
    float4 av1 = __ldg((const float4*)(a_src + tx * 8 + 4));
    float4 bv0 = __ldg((const float4*)(a_dst + tx * 8));
    float4 bv1 = __ldg((const float4*)(a_dst + tx * 8 + 4));
    int head = tx >> 2;

#pragma unroll
    for (int j = 0; j < 8; j++) {
        int row = row0 + ty * 8 + j;
        float ps = acc[j][0] * av0.x + acc[j][1] * av0.y + acc[j][2] * av0.z + acc[j][3] * av0.w
                 + acc[j][4] * av1.x + acc[j][5] * av1.y + acc[j][6] * av1.z + acc[j][7] * av1.w;
        float pd = acc[j][0] * bv0.x + acc[j][1] * bv0.y + acc[j][2] * bv0.z + acc[j][3] * bv0.w
                 + acc[j][4] * bv1.x + acc[j][5] * bv1.y + acc[j][6] * bv1.z + acc[j][7] * bv1.w;
        ps += __shfl_xor_sync(0xffffffff, ps, 1);
        ps += __shfl_xor_sync(0xffffffff, ps, 2);
        pd += __shfl_xor_sync(0xffffffff, pd, 1);
        pd += __shfl_xor_sync(0xffffffff, pd, 2);
        if (row < NN) {
            __half2 hpack[4];
            hpack[0] = __floats2half2_rn(acc[j][0], acc[j][1]);
            hpack[1] = __floats2half2_rn(acc[j][2], acc[j][3]);
            hpack[2] = __floats2half2_rn(acc[j][4], acc[j][5]);
            hpack[3] = __floats2half2_rn(acc[j][6], acc[j][7]);
            *(uint4*)(g_h1h + (size_t)row * 128 + tx * 8) = *(uint4*)hpack;
            if ((tx & 3) == 0) {
                g_as1[row * 4 + head] = ps;
                g_ad1[row * 4 + head] = pd;
            }
        }
    }
}

// ================= fused layer1: warp per node, softmax, fp16 gather =================
__global__ void fused1_kernel(const float* __restrict__ b1) {
    int warp = (blockIdx.x * blockDim.x + threadIdx.x) >> 5;
    int lane = threadIdx.x & 31;
    if (warp >= NN) return;
    int d = warp;
    int head = lane >> 3;
    int start = g_rowstart[d] + g_boff[d >> 8];
    int end = start + g_deg[d] + 1;
    float ad = g_ad1[d * 4 + head];

    float ssum = 0.f;
    float4 acc = make_float4(0.f, 0.f, 0.f, 0.f);
    for (int i = start; i < end; i++) {
        int s = g_csrc[i];
        float p = __expf(lrelu(g_as1[s * 4 + head] + ad));
        ssum += p;
        const __half2* hp = (const __half2*)(g_h1h + (size_t)s * 128 + lane * 4);
        float2 h01 = __half22float2(hp[0]);
        float2 h23 = __half22float2(hp[1]);
        acc.x += p * h01.x;
        acc.y += p * h01.y;
        acc.z += p * h23.x;
        acc.w += p * h23.y;
    }
    float inv = 1.f / fmaxf(ssum, 1e-16f);
    float4 bv = __ldg(&((const float4*)b1)[lane]);
    float4 o;
    o.x = fmaxf(acc.x * inv + bv.x, 0.f);
    o.y = fmaxf(acc.y * inv + bv.y, 0.f);
    o.z = fmaxf(acc.z * inv + bv.z, 0.f);
    o.w = fmaxf(acc.w * inv + bv.w, 0.f);
    *(float4*)(g_o1 + (size_t)d * 128 + lane * 4) = o;
}

// ================= GEMM2 + fused attention-halves epilogue =================
// tile 128 rows x 32 cols, 256 threads, thread tile 4x4. fp16 h2 output.
__global__ void gemm2_kernel(const float* __restrict__ W2,
                             const float* __restrict__ a_src, const float* __restrict__ a_dst) {
    __shared__ float sX[128 * 36];  // 18KB, stride 36
    __shared__ float sW[32 * 32];   // 4KB
    const int t = threadIdx.x;      // 256
    const int tx = t & 7;           // col group (4 cols)
    const int ty = t >> 3;          // row group (4 rows), 0..31
    const int row0 = blockIdx.x * 128;

    float acc[4][4];
#pragma unroll
    for (int j = 0; j < 4; j++)
#pragma unroll
        for (int q = 0; q < 4; q++) acc[j][q] = 0.f;

    for (int kt = 0; kt < 128; kt += 32) {
        __syncthreads();
#pragma unroll
        for (int i = 0; i < 4; i++) {
            int idx = t + i * 256;          // 0..1023
            int r = idx >> 3, kq = idx & 7;
            int row = row0 + r;
            float4 v = make_float4(0.f, 0.f, 0.f, 0.f);
            if (row < NN) v = *(const float4*)(g_o1 + (size_t)row * 128 + kt + kq * 4);
            *(float4*)(sX + r * 36 + kq * 4) = v;
        }
        {
            int k = t >> 3, cq = t & 7;     // 256 threads = 32k x 8 (float4 cols? 32 floats = 8 float4)
            *(float4*)(sW + k * 32 + cq * 4) = *(const float4*)(W2 + (size_t)(kt + k) * 32 + cq * 4);
        }
        __syncthreads();
#pragma unroll
        for (int k = 0; k < 32; k++) {
            float4 wv = *(const float4*)(sW + k * 32 + tx * 4);
#pragma unroll
            for (int j = 0; j < 4; j++) {
                float xv = sX[(ty * 4 + j) * 36 + k];
                acc[j][0] += xv * wv.x;
                acc[j][1] += xv * wv.y;
                acc[j][2] += xv * wv.z;
                acc[j][3] += xv * wv.w;
            }
        }
    }

    float4 av = __ldg((const float4*)(a_src + tx * 4));
    float4 bv = __ldg((const float4*)(a_dst + tx * 4));
#pragma unroll
    for (int j = 0; j < 4; j++) {
        int row = row0 + ty * 4 + j;
        float sp = acc[j][0] * av.x + acc[j][1] * av.y + acc[j][2] * av.z + acc[j][3] * av.w;
        float dp = acc[j][0] * bv.x + acc[j][1] * bv.y + acc[j][2] * bv.z + acc[j][3] * bv.w;
        sp += __shfl_xor_sync(0xffffffff, sp, 1);
        sp += __shfl_xor_sync(0xffffffff, sp, 2);
        sp += __shfl_xor_sync(0xffffffff, sp, 4);
        dp += __shfl_xor_sync(0xffffffff, dp, 1);
        dp += __shfl_xor_sync(0xffffffff, dp, 2);
        dp += __shfl_xor_sync(0xffffffff, dp, 4);
        if (row < NN) {
            __half2 hp0 = __floats2half2_rn(acc[j][0], acc[j][1]);
            __half2 hp1 = __floats2half2_rn(acc[j][2], acc[j][3]);
            *(__half2*)(g_h2h + (size_t)row * 32 + tx * 4) = hp0;
            *(__half2*)(g_h2h + (size_t)row * 32 + tx * 4 + 2) = hp1;
            if (tx == 0) { g_as2[row] = sp; g_ad2[row] = dp; }
        }
    }
}

// ================= fused layer2: warp per node, softmax, sigmoid out =================
__global__ void fused2_kernel(float* __restrict__ out, const float* __restrict__ b2) {
    int warp = (blockIdx.x * blockDim.x + threadIdx.x) >> 5;
    int lane = threadIdx.x & 31;
    if (warp >= NN) return;
    int d = warp;
    int start = g_rowstart[d] + g_boff[d >> 8];
    int end = start + g_deg[d] + 1;
    float ad = g_ad2[d];

    float ssum = 0.f, acc = 0.f;
    for (int i = start; i < end; i++) {
        int s = g_csrc[i];
        float p = __expf(lrelu(g_as2[s] + ad));
        ssum += p;
        acc += p * __half2float(g_h2h[(size_t)s * 32 + lane]);
    }
    float v = acc / fmaxf(ssum, 1e-16f) + __ldg(&b2[lane]);
    out[(size_t)d * 32 + lane] = 1.f / (1.f + __expf(-v));
}

// ================= launcher =================
extern "C" void kernel_launch(void* const* d_in, const int* in_sizes, int n_in,
                              void* d_out, int out_size) {
    const float* x      = (const float*)d_in[0];
    const int*   ei     = (const int*)d_in[1];   // JAX coerces int64 -> int32
    const float* W1     = (const float*)d_in[2];
    const float* a_src1 = (const float*)d_in[3];
    const float* a_dst1 = (const float*)d_in[4];
    const float* b1     = (const float*)d_in[5];
    const float* W2     = (const float*)d_in[6];
    const float* a_src2 = (const float*)d_in[7];
    const float* a_dst2 = (const float*)d_in[8];
    const float* b2     = (const float*)d_in[9];
    float* out = (float*)d_out;

    static cudaStream_t s2 = nullptr;
    static cudaEvent_t evFork = nullptr, evJoin = nullptr;
    if (s2 == nullptr) {
        cudaStreamCreateWithFlags(&s2, cudaStreamNonBlocking);
        cudaEventCreateWithFlags(&evFork, cudaEventDisableTiming);
        cudaEventCreateWithFlags(&evJoin, cudaEventDisableTiming);
    }

    // fork: CSR build on s2, GEMM1 on main stream (independent)
    cudaEventRecord(evFork, 0);
    cudaStreamWaitEvent(s2, evFork, 0);

    zero_deg_kernel<<<NB1, 256, 0, s2>>>();
    hist_kernel<<<(EG + 255) / 256, 256, 0, s2>>>(ei);
    scanA_kernel<<<NB1, 256, 0, s2>>>();
    scanB_kernel<<<1, 256, 0, s2>>>();
    scatter_kernel<<<(EE + 255) / 256, 256, 0, s2>>>(ei);
    cudaEventRecord(evJoin, s2);

    gemm1_kernel<<<(NN + 127) / 128, 256>>>(x, W1, a_src1, a_dst1);

    // join: fused1 needs CSR + gemm1
    cudaStreamWaitEvent(0, evJoin, 0);
    fused1_kernel<<<(NN * 32 + 255) / 256, 256>>>(b1);

    gemm2_kernel<<<(NN + 127) / 128, 256>>>(W2, a_src2, a_dst2);
    fused2_kernel<<<(NN * 32 + 255) / 256, 256>>>(out, b2);
}

// round 7
// speedup vs baseline: 3.1268x; 1.2031x over previous
#include <cuda_runtime.h>
#include <cuda_fp16.h>
#include <stdint.h>
#include <math.h>

#define NN 50000
#define EG 800000
#define EE 850000            // EG + NN self loops
#define NB1 196              // ceil(NN/256)

// ---------------- scratch (device globals; no allocation) ----------------
__device__ __align__(16) __half g_h1h[NN * 128];  // layer1 linear out (fp16)
__device__ __align__(16) __half g_o1h[NN * 128];  // layer1 aggregated+relu out (fp16)
__device__ __align__(16) __half g_h2h[NN * 32];   // layer2 linear out (fp16)
__device__ __align__(16) float g_as1[NN * 4];
__device__ __align__(16) float g_ad1[NN * 4];
__device__ __align__(16) float g_as2[NN];
__device__ __align__(16) float g_ad2[NN];
__device__ int g_deg[NN];        // zero at entry of each call; scanA consumes+resets
__device__ int g_rowstart[NN];   // block-LOCAL exclusive scan of (deg+1)
__device__ int g_cursor[NN];
__device__ int g_psum[NB1];
__device__ int g_boff[NB1 + 1];  // per-block global offsets (+ total)
__device__ int g_csrc[EE];

__device__ __forceinline__ float lrelu(float x) { return x > 0.f ? x : 0.2f * x; }

__device__ __forceinline__ void mma16816(float& c0, float& c1, float& c2, float& c3,
                                         uint32_t a0, uint32_t a1, uint32_t a2, uint32_t a3,
                                         uint32_t b0, uint32_t b1) {
    asm volatile("mma.sync.aligned.m16n8k16.row.col.f32.f16.f16.f32 "
                 "{%0,%1,%2,%3}, {%4,%5,%6,%7}, {%8,%9}, {%0,%1,%2,%3};"
                 : "+f"(c0), "+f"(c1), "+f"(c2), "+f"(c3)
                 : "r"(a0), "r"(a1), "r"(a2), "r"(a3), "r"(b0), "r"(b1));
}

// ================= CSR build (4 kernels) =================
__global__ void hist_kernel(const int* __restrict__ ei) {
    int e = blockIdx.x * blockDim.x + threadIdx.x;
    if (e < EG) atomicAdd(&g_deg[ei[EG + e]], 1);
}

__device__ __forceinline__ int blockScanExclusive(int v, int* sm) {
    int t = threadIdx.x;
    sm[t] = v;
    __syncthreads();
#pragma unroll
    for (int off = 1; off < 256; off <<= 1) {
        int x = (t >= off) ? sm[t - off] : 0;
        __syncthreads();
        sm[t] += x;
        __syncthreads();
    }
    return sm[t] - v;
}

__global__ void scanA_kernel() {
    __shared__ int sm[256];
    int t = threadIdx.x;
    int idx = blockIdx.x * 256 + t;
    int v = (idx < NN) ? g_deg[idx] + 1 : 0;
    int ex = blockScanExclusive(v, sm);
    if (idx < NN) {
        g_rowstart[idx] = ex;
        g_cursor[idx] = ex;
        g_deg[idx] = 0;               // reset for next call (deterministic across replays)
    }
    if (t == 255) g_psum[blockIdx.x] = ex + v;
}

__global__ void scanB_kernel() {   // 1 block, 256 threads
    __shared__ int sm[256];
    int t = threadIdx.x;
    int v = (t < NB1) ? g_psum[t] : 0;
    int ex = blockScanExclusive(v, sm);
    if (t < NB1) g_boff[t] = ex;
    if (t == NB1 - 1) g_boff[NB1] = ex + v;
}

__global__ void scatter_kernel(const int* __restrict__ ei) {
    int e = blockIdx.x * blockDim.x + threadIdx.x;
    if (e >= EE) return;
    int s, d;
    if (e < EG) { s = ei[e]; d = ei[EG + e]; }
    else        { s = d = e - EG; }
    int pos = atomicAdd(&g_cursor[d], 1) + g_boff[d >> 8];
    g_csrc[pos] = s;
}

__device__ __forceinline__ void rowRange(int d, int& start, int& end) {
    int blk = d >> 8;
    int boff = g_boff[blk];
    start = g_rowstart[d] + boff;
    bool last = ((d & 255) == 255) || (d == NN - 1);
    end = last ? g_boff[blk + 1] : (g_rowstart[d + 1] + boff);
}

// ================= GEMM1 (tensor core) + attention-halves epilogue =================
// tile 128x128, K=128 in two 64-k stages. 8 warps: 4(m) x 2(n), warp tile 32x64.
#define P1 72   // smem k-pitch (halves)
__global__ void __launch_bounds__(256) gemm1_kernel(
        const float* __restrict__ x, const float* __restrict__ W,
        const float* __restrict__ a_src, const float* __restrict__ a_dst) {
    __shared__ __half sA[128 * P1];
    __shared__ __half sB[128 * P1];   // sB[n][k]
    const int t = threadIdx.x;
    const int wid = t >> 5, lane = t & 31;
    const int wm = wid >> 1, wn = wid & 1;
    const int q = lane >> 2, g = lane & 3;
    const int row0 = blockIdx.x * 128;

    float c[2][8][4];
#pragma unroll
    for (int mt = 0; mt < 2; mt++)
#pragma unroll
        for (int nt = 0; nt < 8; nt++)
#pragma unroll
            for (int j = 0; j < 4; j++) c[mt][nt][j] = 0.f;

    for (int kt = 0; kt < 128; kt += 64) {
        __syncthreads();
        // A: 128 rows x 64 k, fp32 -> fp16 (2048 float4 loads)
#pragma unroll
        for (int i = 0; i < 8; i++) {
            int idx = t + i * 256;            // 0..2047
            int r = idx >> 4, c4 = idx & 15;
            int row = row0 + r;
            float4 v = make_float4(0.f, 0.f, 0.f, 0.f);
            if (row < NN) v = *(const float4*)(x + (size_t)row * 128 + kt + c4 * 4);
            *(__half2*)(sA + r * P1 + c4 * 4)     = __floats2half2_rn(v.x, v.y);
            *(__half2*)(sA + r * P1 + c4 * 4 + 2) = __floats2half2_rn(v.z, v.w);
        }
        // B: W[kt..kt+64)[128] fp32, transposed -> sB[n][k] fp16
#pragma unroll
        for (int i = 0; i < 8; i++) {
            int idx = t + i * 256;
            int k = idx >> 5, c4 = idx & 31;
            float4 v = *(const float4*)(W + (size_t)(kt + k) * 128 + c4 * 4);
            sB[(c4 * 4 + 0) * P1 + k] = __float2half_rn(v.x);
            sB[(c4 * 4 + 1) * P1 + k] = __float2half_rn(v.y);
            sB[(c4 * 4 + 2) * P1 + k] = __float2half_rn(v.z);
            sB[(c4 * 4 + 3) * P1 + k] = __float2half_rn(v.w);
        }
        __syncthreads();
#pragma unroll
        for (int ks = 0; ks < 4; ks++) {
            int kk = ks * 16 + 2 * g;
            uint32_t a[2][4];
#pragma unroll
            for (int mt = 0; mt < 2; mt++) {
                int r = wm * 32 + mt * 16 + q;
                a[mt][0] = *(const uint32_t*)(sA + r * P1 + kk);
                a[mt][1] = *(const uint32_t*)(sA + (r + 8) * P1 + kk);
                a[mt][2] = *(const uint32_t*)(sA + r * P1 + kk + 8);
                a[mt][3] = *(const uint32_t*)(sA + (r + 8) * P1 + kk + 8);
            }
#pragma unroll
            for (int nt = 0; nt < 8; nt++) {
                int n = wn * 64 + nt * 8 + q;
                uint32_t b0 = *(const uint32_t*)(sB + n * P1 + kk);
                uint32_t b1 = *(const uint32_t*)(sB + n * P1 + kk + 8);
                mma16816(c[0][nt][0], c[0][nt][1], c[0][nt][2], c[0][nt][3],
                         a[0][0], a[0][1], a[0][2], a[0][3], b0, b1);
                mma16816(c[1][nt][0], c[1][nt][1], c[1][nt][2], c[1][nt][3],
                         a[1][0], a[1][1], a[1][2], a[1][3], b0, b1);
            }
        }
    }

    // epilogue: store h1h fp16 + per-row per-head attention dots
    float2 av[8], bv[8];
#pragma unroll
    for (int nt = 0; nt < 8; nt++) {
        int col0 = wn * 64 + nt * 8 + 2 * g;
        av[nt] = *(const float2*)(a_src + col0);
        bv[nt] = *(const float2*)(a_dst + col0);
    }
#pragma unroll
    for (int mt = 0; mt < 2; mt++) {
        int r = row0 + wm * 32 + mt * 16 + q;
        float ps0[2] = {0.f, 0.f}, ps1[2] = {0.f, 0.f};
        float pd0[2] = {0.f, 0.f}, pd1[2] = {0.f, 0.f};
#pragma unroll
        for (int nt = 0; nt < 8; nt++) {
            int hl = nt >> 2;
            ps0[hl] += c[mt][nt][0] * av[nt].x + c[mt][nt][1] * av[nt].y;
            pd0[hl] += c[mt][nt][0] * bv[nt].x + c[mt][nt][1] * bv[nt].y;
            ps1[hl] += c[mt][nt][2] * av[nt].x + c[mt][nt][3] * av[nt].y;
            pd1[hl] += c[mt][nt][2] * bv[nt].x + c[mt][nt][3] * bv[nt].y;
            int col0 = wn * 64 + nt * 8 + 2 * g;
            if (r < NN)
                *(__half2*)(g_h1h + (size_t)r * 128 + col0) =
                    __floats2half2_rn(c[mt][nt][0], c[mt][nt][1]);
            if (r + 8 < NN)
                *(__half2*)(g_h1h + (size_t)(r + 8) * 128 + col0) =
                    __floats2half2_rn(c[mt][nt][2], c[mt][nt][3]);
        }
#pragma unroll
        for (int hl = 0; hl < 2; hl++) {
            float s0 = ps0[hl], s1 = ps1[hl], d0 = pd0[hl], d1 = pd1[hl];
            s0 += __shfl_xor_sync(0xffffffff, s0, 1); s0 += __shfl_xor_sync(0xffffffff, s0, 2);
            s1 += __shfl_xor_sync(0xffffffff, s1, 1); s1 += __shfl_xor_sync(0xffffffff, s1, 2);
            d0 += __shfl_xor_sync(0xffffffff, d0, 1); d0 += __shfl_xor_sync(0xffffffff, d0, 2);
            d1 += __shfl_xor_sync(0xffffffff, d1, 1); d1 += __shfl_xor_sync(0xffffffff, d1, 2);
            int hg = wn * 2 + hl;
            if (g == 0) {
                if (r < NN)     { g_as1[r * 4 + hg] = s0;       g_ad1[r * 4 + hg] = d0; }
                if (r + 8 < NN) { g_as1[(r + 8) * 4 + hg] = s1; g_ad1[(r + 8) * 4 + hg] = d1; }
            }
        }
    }
}

// ================= fused layer1: warp per node, softmax, fp16 gather =================
__global__ void fused1_kernel(const float* __restrict__ b1) {
    int warp = (blockIdx.x * blockDim.x + threadIdx.x) >> 5;
    int lane = threadIdx.x & 31;
    if (warp >= NN) return;
    int d = warp;
    int head = lane >> 3;
    int start, end;
    rowRange(d, start, end);
    float ad = g_ad1[d * 4 + head];

    float ssum = 0.f;
    float4 acc = make_float4(0.f, 0.f, 0.f, 0.f);
    int i = start;
    for (; i + 2 <= end; i += 2) {
        int s0 = g_csrc[i], s1 = g_csrc[i + 1];
        float p0 = __expf(lrelu(g_as1[s0 * 4 + head] + ad));
        float p1 = __expf(lrelu(g_as1[s1 * 4 + head] + ad));
        uint2 r0 = *(const uint2*)(g_h1h + (size_t)s0 * 128 + lane * 4);
        uint2 r1 = *(const uint2*)(g_h1h + (size_t)s1 * 128 + lane * 4);
        float2 h0a = __half22float2(*(__half2*)&r0.x);
        float2 h0b = __half22float2(*(__half2*)&r0.y);
        float2 h1a = __half22float2(*(__half2*)&r1.x);
        float2 h1b = __half22float2(*(__half2*)&r1.y);
        ssum += p0 + p1;
        acc.x += p0 * h0a.x + p1 * h1a.x;
        acc.y += p0 * h0a.y + p1 * h1a.y;
        acc.z += p0 * h0b.x + p1 * h1b.x;
        acc.w += p0 * h0b.y + p1 * h1b.y;
    }
    if (i < end) {
        int s0 = g_csrc[i];
        float p0 = __expf(lrelu(g_as1[s0 * 4 + head] + ad));
        uint2 r0 = *(const uint2*)(g_h1h + (size_t)s0 * 128 + lane * 4);
        float2 h0a = __half22float2(*(__half2*)&r0.x);
        float2 h0b = __half22float2(*(__half2*)&r0.y);
        ssum += p0;
        acc.x += p0 * h0a.x; acc.y += p0 * h0a.y;
        acc.z += p0 * h0b.x; acc.w += p0 * h0b.y;
    }
    float inv = 1.f / fmaxf(ssum, 1e-16f);
    float4 bvv = __ldg(&((const float4*)b1)[lane]);
    __half2 o0 = __floats2half2_rn(fmaxf(acc.x * inv + bvv.x, 0.f),
                                   fmaxf(acc.y * inv + bvv.y, 0.f));
    __half2 o1 = __floats2half2_rn(fmaxf(acc.z * inv + bvv.z, 0.f),
                                   fmaxf(acc.w * inv + bvv.w, 0.f));
    uint2 packed;
    packed.x = *(uint32_t*)&o0;
    packed.y = *(uint32_t*)&o1;
    *(uint2*)(g_o1h + (size_t)d * 128 + lane * 4) = packed;
}

// ================= GEMM2 (tensor core) + attention-halves epilogue =================
// tile 128x32, K=128 single stage. 8 warps, each 16(m) x 32(n).
#define P2 136
__global__ void __launch_bounds__(256) gemm2_kernel(
        const float* __restrict__ W2,
        const float* __restrict__ a_src, const float* __restrict__ a_dst) {
    __shared__ __half sA[128 * P2];  // ~34.8KB
    __shared__ __half sB[32 * P2];   // ~8.7KB
    const int t = threadIdx.x;
    const int wid = t >> 5, lane = t & 31;
    const int q = lane >> 2, g = lane & 3;
    const int row0 = blockIdx.x * 128;

    float c[4][4];
#pragma unroll
    for (int nt = 0; nt < 4; nt++)
#pragma unroll
        for (int j = 0; j < 4; j++) c[nt][j] = 0.f;

    // A: g_o1h (already fp16), 128 rows x 128 halves = 128 rows x 16 uint4 = 2048 uint4
#pragma unroll
    for (int i = 0; i < 8; i++) {
        int idx = t + i * 256;          // 0..2047
        int r = idx >> 4, c8 = idx & 15;   // FIXED: 16 uint4 per row (was >>3/&7: smem OOB)
        int row = row0 + r;
        uint4 v = make_uint4(0u, 0u, 0u, 0u);
        if (row < NN) v = *(const uint4*)(g_o1h + (size_t)row * 128 + c8 * 8);
        *(uint4*)(sA + r * P2 + c8 * 8) = v;
    }
    // B: W2 [128k][32n] fp32 -> sB[n][k]
#pragma unroll
    for (int i = 0; i < 4; i++) {
        int idx = t + i * 256;          // 0..1023
        int k = idx >> 3, c4 = idx & 7;
        float4 v = *(const float4*)(W2 + (size_t)k * 32 + c4 * 4);
        sB[(c4 * 4 + 0) * P2 + k] = __float2half_rn(v.x);
        sB[(c4 * 4 + 1) * P2 + k] = __float2half_rn(v.y);
        sB[(c4 * 4 + 2) * P2 + k] = __float2half_rn(v.z);
        sB[(c4 * 4 + 3) * P2 + k] = __float2half_rn(v.w);
    }
    __syncthreads();

#pragma unroll
    for (int ks = 0; ks < 8; ks++) {
        int kk = ks * 16 + 2 * g;
        int r = wid * 16 + q;
        uint32_t a0 = *(const uint32_t*)(sA + r * P2 + kk);
        uint32_t a1 = *(const uint32_t*)(sA + (r + 8) * P2 + kk);
        uint32_t a2 = *(const uint32_t*)(sA + r * P2 + kk + 8);
        uint32_t a3 = *(const uint32_t*)(sA + (r + 8) * P2 + kk + 8);
#pragma unroll
        for (int nt = 0; nt < 4; nt++) {
            int n = nt * 8 + q;
            uint32_t b0 = *(const uint32_t*)(sB + n * P2 + kk);
            uint32_t b1 = *(const uint32_t*)(sB + n * P2 + kk + 8);
            mma16816(c[nt][0], c[nt][1], c[nt][2], c[nt][3], a0, a1, a2, a3, b0, b1);
        }
    }

    // epilogue
    float2 av[4], bv[4];
#pragma unroll
    for (int nt = 0; nt < 4; nt++) {
        int col0 = nt * 8 + 2 * g;
        av[nt] = *(const float2*)(a_src + col0);
        bv[nt] = *(const float2*)(a_dst + col0);
    }
    int r = row0 + wid * 16 + q;
    float ps0 = 0.f, ps1 = 0.f, pd0 = 0.f, pd1 = 0.f;
#pragma unroll
    for (int nt = 0; nt < 4; nt++) {
        ps0 += c[nt][0] * av[nt].x + c[nt][1] * av[nt].y;
        pd0 += c[nt][0] * bv[nt].x + c[nt][1] * bv[nt].y;
        ps1 += c[nt][2] * av[nt].x + c[nt][3] * av[nt].y;
        pd1 += c[nt][2] * bv[nt].x + c[nt][3] * bv[nt].y;
        int col0 = nt * 8 + 2 * g;
        if (r < NN)
            *(__half2*)(g_h2h + (size_t)r * 32 + col0) = __floats2half2_rn(c[nt][0], c[nt][1]);
        if (r + 8 < NN)
            *(__half2*)(g_h2h + (size_t)(r + 8) * 32 + col0) = __floats2half2_rn(c[nt][2], c[nt][3]);
    }
    ps0 += __shfl_xor_sync(0xffffffff, ps0, 1); ps0 += __shfl_xor_sync(0xffffffff, ps0, 2);
    ps1 += __shfl_xor_sync(0xffffffff, ps1, 1); ps1 += __shfl_xor_sync(0xffffffff, ps1, 2);
    pd0 += __shfl_xor_sync(0xffffffff, pd0, 1); pd0 += __shfl_xor_sync(0xffffffff, pd0, 2);
    pd1 += __shfl_xor_sync(0xffffffff, pd1, 1); pd1 += __shfl_xor_sync(0xffffffff, pd1, 2);
    if (g == 0) {
        if (r < NN)     { g_as2[r] = ps0;     g_ad2[r] = pd0; }
        if (r + 8 < NN) { g_as2[r + 8] = ps1; g_ad2[r + 8] = pd1; }
    }
}

// ================= fused layer2: warp per node, softmax, sigmoid out =================
__global__ void fused2_kernel(float* __restrict__ out, const float* __restrict__ b2) {
    int warp = (blockIdx.x * blockDim.x + threadIdx.x) >> 5;
    int lane = threadIdx.x & 31;
    if (warp >= NN) return;
    int d = warp;
    int start, end;
    rowRange(d, start, end);
    float ad = g_ad2[d];

    float ssum = 0.f, acc = 0.f;
    int i = start;
    for (; i + 2 <= end; i += 2) {
        int s0 = g_csrc[i], s1 = g_csrc[i + 1];
        float p0 = __expf(lrelu(g_as2[s0] + ad));
        float p1 = __expf(lrelu(g_as2[s1] + ad));
        float h0 = __half2float(g_h2h[(size_t)s0 * 32 + lane]);
        float h1 = __half2float(g_h2h[(size_t)s1 * 32 + lane]);
        ssum += p0 + p1;
        acc += p0 * h0 + p1 * h1;
    }
    if (i < end) {
        int s0 = g_csrc[i];
        float p0 = __expf(lrelu(g_as2[s0] + ad));
        ssum += p0;
        acc += p0 * __half2float(g_h2h[(size_t)s0 * 32 + lane]);
    }
    float v = acc / fmaxf(ssum, 1e-16f) + __ldg(&b2[lane]);
    out[(size_t)d * 32 + lane] = 1.f / (1.f + __expf(-v));
}

// ================= launcher =================
extern "C" void kernel_launch(void* const* d_in, const int* in_sizes, int n_in,
                              void* d_out, int out_size) {
    const float* x      = (const float*)d_in[0];
    const int*   ei     = (const int*)d_in[1];   // JAX coerces int64 -> int32
    const float* W1     = (const float*)d_in[2];
    const float* a_src1 = (const float*)d_in[3];
    const float* a_dst1 = (const float*)d_in[4];
    const float* b1     = (const float*)d_in[5];
    const float* W2     = (const float*)d_in[6];
    const float* a_src2 = (const float*)d_in[7];
    const float* a_dst2 = (const float*)d_in[8];
    const float* b2     = (const float*)d_in[9];
    float* out = (float*)d_out;

    static cudaStream_t s2 = nullptr;
    static cudaEvent_t evFork = nullptr, evJoin = nullptr;
    if (s2 == nullptr) {
        cudaStreamCreateWithFlags(&s2, cudaStreamNonBlocking);
        cudaEventCreateWithFlags(&evFork, cudaEventDisableTiming);
        cudaEventCreateWithFlags(&evJoin, cudaEventDisableTiming);
    }

    // fork: CSR build on s2, GEMM1 on main stream (independent)
    cudaEventRecord(evFork, 0);
    cudaStreamWaitEvent(s2, evFork, 0);

    hist_kernel<<<(EG + 255) / 256, 256, 0, s2>>>(ei);
    scanA_kernel<<<NB1, 256, 0, s2>>>();
    scanB_kernel<<<1, 256, 0, s2>>>();
    scatter_kernel<<<(EE + 255) / 256, 256, 0, s2>>>(ei);
    cudaEventRecord(evJoin, s2);

    gemm1_kernel<<<(NN + 127) / 128, 256>>>(x, W1, a_src1, a_dst1);

    // join: fused1 needs CSR + gemm1
    cudaStreamWaitEvent(0, evJoin, 0);
    fused1_kernel<<<(NN * 32 + 255) / 256, 256>>>(b1);

    gemm2_kernel<<<(NN + 127) / 128, 256>>>(W2, a_src2, a_dst2);
    fused2_kernel<<<(NN * 32 + 255) / 256, 256>>>(out, b2);
}